// round 6
// baseline (speedup 1.0000x reference)
#include <cuda_runtime.h>

#define G_SEG   20000
#define M_MEM   5120000
#define D_FEAT  256
#define R_REP   4

#define NTHREADS      256
#define MEMBER_WARPS  6                       // warps 0-5: member scatter
#define GEMV_WARPS    2                       // warps 6-7: GEMV
#define MEMBER_WITERS (M_MEM / 8 / 32)        // 20000 warp-iterations (8 members/thread)

// Replicated per-glimpse accumulators: {sum_e, sum_e*px, sum_e*py, sum_e*pz}.
// 4 * 20000 * 16B = 1.25 MB, L2-resident. Zero-initialized at module load;
// the in-kernel finalize re-zeroes after reading, so every replay starts clean.
__device__ float4 g_acc[R_REP][G_SEG];

// Grid barrier state. Zero-initialized; last departer resets both to zero so
// the state is identical at the start of every graph replay.
__device__ unsigned int g_arrive;
__device__ unsigned int g_depart;

// One vectorized reduction per member: red.global.add.v4.f32 (sm_90+).
__device__ __forceinline__ void red_v4(float4* p, float a, float b, float c, float d) {
    asm volatile("red.global.add.v4.f32 [%0], {%1, %2, %3, %4};"
                 :: "l"(p), "f"(a), "f"(b), "f"(c), "f"(d)
                 : "memory");
}

// Persistent single-wave kernel: member scatter + GEMV, software grid barrier,
// then finalize against hot-L2 accumulators. Launched with exactly
// (SMs x resident-blocks-per-SM) blocks so all blocks are co-resident.
__global__ __launch_bounds__(NTHREADS, 4) void persistent_kernel(
    const float4* __restrict__ pos4,
    const float4* __restrict__ lm4,
    const int4*   __restrict__ idx4,
    const float*  __restrict__ gf,     // (G, 256)
    const float*  __restrict__ Wv,     // (256,)
    const float*  __restrict__ bv,     // (1,)
    const float*  __restrict__ u,      // (G,)
    const float*  __restrict__ temp,   // scalar
    float*        __restrict__ out)    // (G, 5)
{
    const int wid  = threadIdx.x >> 5;
    const int lane = threadIdx.x & 31;

    if (wid < MEMBER_WARPS) {
        // ---- member scatter-reduce: grid-stride over 20000 warp-iters ----
        const int wstride = MEMBER_WARPS * gridDim.x;
        for (int w = blockIdx.x * MEMBER_WARPS + wid; w < MEMBER_WITERS; w += wstride) {
            const int t = w * 32 + lane;          // thread item, 8 members each

            // Front-batch all 10 vector loads to maximize MLP before the
            // dependent exp/REDG chain.
            float4 lmA = lm4[2 * t + 0];
            float4 lmB = lm4[2 * t + 1];
            int4   ixA = idx4[2 * t + 0];
            int4   ixB = idx4[2 * t + 1];
            float4 p0 = pos4[6 * t + 0];
            float4 p1 = pos4[6 * t + 1];
            float4 p2 = pos4[6 * t + 2];
            float4 p3 = pos4[6 * t + 3];
            float4 p4 = pos4[6 * t + 4];
            float4 p5 = pos4[6 * t + 5];

            float eA0 = __expf(lmA.x), eA1 = __expf(lmA.y);
            float eA2 = __expf(lmA.z), eA3 = __expf(lmA.w);
            float eB0 = __expf(lmB.x), eB1 = __expf(lmB.y);
            float eB2 = __expf(lmB.z), eB3 = __expf(lmB.w);

            float4* acc = g_acc[w & (R_REP - 1)];

            red_v4(&acc[ixA.x], eA0, eA0 * p0.x, eA0 * p0.y, eA0 * p0.z);
            red_v4(&acc[ixA.y], eA1, eA1 * p0.w, eA1 * p1.x, eA1 * p1.y);
            red_v4(&acc[ixA.z], eA2, eA2 * p1.z, eA2 * p1.w, eA2 * p2.x);
            red_v4(&acc[ixA.w], eA3, eA3 * p2.y, eA3 * p2.z, eA3 * p2.w);
            red_v4(&acc[ixB.x], eB0, eB0 * p3.x, eB0 * p3.y, eB0 * p3.z);
            red_v4(&acc[ixB.y], eB1, eB1 * p3.w, eB1 * p4.x, eB1 * p4.y);
            red_v4(&acc[ixB.z], eB2, eB2 * p4.z, eB2 * p4.w, eB2 * p5.x);
            red_v4(&acc[ixB.w], eB3, eB3 * p5.y, eB3 * p5.z, eB3 * p5.w);
        }
    } else {
        // ---- warp-per-glimpse GEMV: grid-stride over 20000 glimpses ----
        const int gstride = GEMV_WARPS * gridDim.x;
        const float4* w4 = (const float4*)Wv;
        for (int g = blockIdx.x * GEMV_WARPS + (wid - MEMBER_WARPS); g < G_SEG; g += gstride) {
            const float4* row = (const float4*)(gf + (size_t)g * D_FEAT);

            float s = 0.f;
#pragma unroll
            for (int k = 0; k < 2; k++) {
                float4 a = row[lane + 32 * k];
                float4 w = w4[lane + 32 * k];
                s += a.x * w.x + a.y * w.y + a.z * w.z + a.w * w.w;
            }
#pragma unroll
            for (int o = 16; o; o >>= 1) s += __shfl_xor_sync(0xFFFFFFFFu, s, o);

            if (lane == 0) {
                float logit = 8.8f * tanhf(s + bv[0]);
                float uu = u[g];
                float relaxed = (logit + logf(uu) - log1pf(-uu)) / temp[0];
                float lzp = fminf(relaxed, 0.f) - log1pf(__expf(-fabsf(relaxed)));
                float* o5 = out + (size_t)g * 5;
                o5[0] = lzp;
                o5[1] = logit;
            }
        }
    }

    // ---- grid barrier (all blocks co-resident by construction) ----
    __syncthreads();
    if (threadIdx.x == 0) {
        __threadfence();                      // make this block's REDGs visible
        atomicAdd(&g_arrive, 1u);
        while (*(volatile unsigned int*)&g_arrive < gridDim.x) { }
    }
    __syncthreads();
    __threadfence();                          // acquire all blocks' REDGs

    // ---- finalize: thread per (glimpse, replica), replicas lane-aligned ----
    const int nt = gridDim.x * NTHREADS;
    for (int t = blockIdx.x * NTHREADS + threadIdx.x; t < G_SEG * R_REP; t += nt) {
        const int g = t >> 2;
        const int r = t & 3;

        float4 a = g_acc[r][g];
        g_acc[r][g] = make_float4(0.f, 0.f, 0.f, 0.f);   // clean for next replay

#pragma unroll
        for (int o = 2; o; o >>= 1) {
            a.x += __shfl_xor_sync(0xFFFFFFFFu, a.x, o);
            a.y += __shfl_xor_sync(0xFFFFFFFFu, a.y, o);
            a.z += __shfl_xor_sync(0xFFFFFFFFu, a.z, o);
            a.w += __shfl_xor_sync(0xFFFFFFFFu, a.w, o);
        }

        if (r == 0) {
            float inv = 1.f / a.x;
            float* o5 = out + (size_t)g * 5;
            o5[2] = a.y * inv;
            o5[3] = a.z * inv;
            o5[4] = a.w * inv;
        }
    }

    // ---- depart: last block resets barrier state for the next replay ----
    __syncthreads();
    if (threadIdx.x == 0) {
        unsigned int old = atomicAdd(&g_depart, 1u);
        if (old == gridDim.x - 1) {
            g_arrive = 0u;                    // everyone is past the arrive spin
            g_depart = 0u;
            __threadfence();
        }
    }
}

extern "C" void kernel_launch(void* const* d_in, const int* in_sizes, int n_in,
                              void* d_out, int out_size)
{
    const float* gf   = (const float*)d_in[0];   // glimpse_feature (G, 256)
    const float* pos  = (const float*)d_in[1];   // member_local_pos (M, 3)
    const float* lm   = (const float*)d_in[2];   // member_log_mask (M, 1)
    const int*   idx  = (const int*)  d_in[3];   // member_glimpse_index (M,)
    const float* u    = (const float*)d_in[4];   // u (G,)
    const float* Wv   = (const float*)d_in[5];   // W (256, 1)
    const float* bv   = (const float*)d_in[6];   // b (1,)
    const float* temp = (const float*)d_in[7];   // temperature scalar

    // Single-wave grid: all blocks resident -> spin barrier cannot deadlock.
    int dev = 0, sms = 0, per_sm = 0;
    cudaGetDevice(&dev);
    cudaDeviceGetAttribute(&sms, cudaDevAttrMultiProcessorCount, dev);
    cudaOccupancyMaxActiveBlocksPerMultiprocessor(&per_sm, persistent_kernel, NTHREADS, 0);
    if (sms <= 0)   sms = 148;
    if (per_sm < 1) per_sm = 1;
    const int nblk = sms * per_sm;

    persistent_kernel<<<nblk, NTHREADS>>>(
        (const float4*)pos, (const float4*)lm, (const int4*)idx,
        gf, Wv, bv, u, temp, (float*)d_out);
}

// round 7
// speedup vs baseline: 1.3476x; 1.3476x over previous
#include <cuda_runtime.h>

#define G_SEG   20000
#define M_MEM   5120000
#define D_FEAT  256
#define R_REP   2

#define MEMBER_BLOCKS 2500            // (M/8)/256
#define GEMV_BLOCKS   2500            // 20000 warps / 8 warps per block

// Replicated per-glimpse accumulators: {sum_e, sum_e*px, sum_e*py, sum_e*pz}.
// 2 * 20000 * 16B = 640 KB, L2-resident. Zero-initialized at module load;
// finalize_kernel re-zeroes after reading, so every graph replay starts clean.
__device__ float4 g_acc[R_REP][G_SEG];

// One vectorized reduction per member: red.global.add.v4.f32 (sm_90+).
__device__ __forceinline__ void red_v4(float4* p, float a, float b, float c, float d) {
    asm volatile("red.global.add.v4.f32 [%0], {%1, %2, %3, %4};"
                 :: "l"(p), "f"(a), "f"(b), "f"(c), "f"(d)
                 : "memory");
}

// Fused kernel, interleaved roles (R5 structure — best measured member path):
//   even blocks -> member scatter-reduce (8 members/thread, front-batched loads)
//   odd  blocks -> GEMV + presence logits (DRAM-streaming)
__global__ __launch_bounds__(256) void fused_kernel(
    const float4* __restrict__ pos4,
    const float4* __restrict__ lm4,
    const int4*   __restrict__ idx4,
    const float*  __restrict__ gf,     // (G, 256)
    const float*  __restrict__ Wv,     // (256,)
    const float*  __restrict__ bv,     // (1,)
    const float*  __restrict__ u,      // (G,)
    const float*  __restrict__ temp,   // scalar
    float*        __restrict__ out)    // (G, 5)
{
    if ((blockIdx.x & 1) == 0) {
        // ---- member scatter-reduce: 8 members per thread ----
        int t = (blockIdx.x >> 1) * blockDim.x + threadIdx.x;  // 0 .. M/8-1 exact

        // Front-batch all 10 vector loads to maximize MLP before the
        // dependent exp/REDG chain.
        float4 lmA = lm4[2 * t + 0];
        float4 lmB = lm4[2 * t + 1];
        int4   ixA = idx4[2 * t + 0];
        int4   ixB = idx4[2 * t + 1];
        float4 p0 = pos4[6 * t + 0];
        float4 p1 = pos4[6 * t + 1];
        float4 p2 = pos4[6 * t + 2];
        float4 p3 = pos4[6 * t + 3];
        float4 p4 = pos4[6 * t + 4];
        float4 p5 = pos4[6 * t + 5];

        float eA0 = __expf(lmA.x), eA1 = __expf(lmA.y);
        float eA2 = __expf(lmA.z), eA3 = __expf(lmA.w);
        float eB0 = __expf(lmB.x), eB1 = __expf(lmB.y);
        float eB2 = __expf(lmB.z), eB3 = __expf(lmB.w);

        // Per-warp replica choice spreads concurrent warps across replicas.
        int rep = ((blockIdx.x << 3) + (threadIdx.x >> 5)) & (R_REP - 1);
        float4* acc = g_acc[rep];

        // quad A: members 8t..8t+3, positions p0..p2
        red_v4(&acc[ixA.x], eA0, eA0 * p0.x, eA0 * p0.y, eA0 * p0.z);
        red_v4(&acc[ixA.y], eA1, eA1 * p0.w, eA1 * p1.x, eA1 * p1.y);
        red_v4(&acc[ixA.z], eA2, eA2 * p1.z, eA2 * p1.w, eA2 * p2.x);
        red_v4(&acc[ixA.w], eA3, eA3 * p2.y, eA3 * p2.z, eA3 * p2.w);
        // quad B: members 8t+4..8t+7, positions p3..p5
        red_v4(&acc[ixB.x], eB0, eB0 * p3.x, eB0 * p3.y, eB0 * p3.z);
        red_v4(&acc[ixB.y], eB1, eB1 * p3.w, eB1 * p4.x, eB1 * p4.y);
        red_v4(&acc[ixB.z], eB2, eB2 * p4.z, eB2 * p4.w, eB2 * p5.x);
        red_v4(&acc[ixB.w], eB3, eB3 * p5.y, eB3 * p5.z, eB3 * p5.w);
    } else {
        // ---- warp-per-glimpse GEMV: 8 warps/block ----
        int gw   = (blockIdx.x >> 1) * 8 + (threadIdx.x >> 5);
        int lane = threadIdx.x & 31;
        if (gw >= G_SEG) return;

        const float4* row = (const float4*)(gf + (size_t)gw * D_FEAT);
        const float4* w4  = (const float4*)Wv;

        float s = 0.f;
#pragma unroll
        for (int k = 0; k < 2; k++) {
            float4 a = row[lane + 32 * k];
            float4 w = w4[lane + 32 * k];
            s += a.x * w.x + a.y * w.y + a.z * w.z + a.w * w.w;
        }
#pragma unroll
        for (int o = 16; o; o >>= 1) s += __shfl_xor_sync(0xFFFFFFFFu, s, o);

        if (lane == 0) {
            float logit = 8.8f * tanhf(s + bv[0]);
            float uu = u[gw];
            float relaxed = (logit + logf(uu) - log1pf(-uu)) / temp[0];
            float lzp = fminf(relaxed, 0.f) - log1pf(__expf(-fabsf(relaxed)));
            float* o5 = out + (size_t)gw * 5;
            o5[0] = lzp;
            o5[1] = logit;
        }
    }
}

// Slim finalize: one thread per glimpse; two independent replica loads,
// sum, normalize, write cols 2-4, re-zero for the next graph replay.
__global__ __launch_bounds__(128) void finalize_kernel(float* __restrict__ out)
{
    int g = blockIdx.x * blockDim.x + threadIdx.x;
    if (g >= G_SEG) return;

    float4 a = g_acc[0][g];
    float4 b = g_acc[1][g];
    g_acc[0][g] = make_float4(0.f, 0.f, 0.f, 0.f);
    g_acc[1][g] = make_float4(0.f, 0.f, 0.f, 0.f);

    float inv = 1.f / (a.x + b.x);
    float* o5 = out + (size_t)g * 5;
    o5[2] = (a.y + b.y) * inv;
    o5[3] = (a.z + b.z) * inv;
    o5[4] = (a.w + b.w) * inv;
}

extern "C" void kernel_launch(void* const* d_in, const int* in_sizes, int n_in,
                              void* d_out, int out_size)
{
    const float* gf   = (const float*)d_in[0];   // glimpse_feature (G, 256)
    const float* pos  = (const float*)d_in[1];   // member_local_pos (M, 3)
    const float* lm   = (const float*)d_in[2];   // member_log_mask (M, 1)
    const int*   idx  = (const int*)  d_in[3];   // member_glimpse_index (M,)
    const float* u    = (const float*)d_in[4];   // u (G,)
    const float* Wv   = (const float*)d_in[5];   // W (256, 1)
    const float* bv   = (const float*)d_in[6];   // b (1,)
    const float* temp = (const float*)d_in[7];   // temperature scalar

    fused_kernel<<<MEMBER_BLOCKS + GEMV_BLOCKS, 256>>>(
        (const float4*)pos, (const float4*)lm, (const int4*)idx,
        gf, Wv, bv, u, temp, (float*)d_out);

    finalize_kernel<<<(G_SEG + 127) / 128, 128>>>((float*)d_out);
}